// round 4
// baseline (speedup 1.0000x reference)
#include <cuda_runtime.h>
#include <math.h>

// Problem constants (fixed by the reference)
#define NN 100000      // nodes
#define NE 1600000     // edges
#define FI 192         // input feats (64 latent + 128 X)
#define FH 128         // hidden feats
#define BN_EPS 1e-5f

// ---------------- device scratch (no allocs allowed) ----------------
__device__ __align__(128) float g_h1  [(size_t)NN * FH];   // 51.2 MB
__device__ __align__(128) float g_agg1[(size_t)NN * FH];   // 51.2 MB
__device__ __align__(16)  float g_h2  [(size_t)NN * 2];
__device__ __align__(16)  float g_agg2[(size_t)NN * 2];
__device__ float g_dinv[NN];
__device__ int   g_deg [NN];
__device__ float g_sum1[FH], g_sq1[FH];
__device__ __align__(16) float g_scale1[FH];
__device__ __align__(16) float g_shift1[FH];
__device__ float g_sum2[2], g_sq2[2];
__device__ int   g_is64;

// ---------------- init: zero accumulators + detect edge dtype ----------------
__global__ void k_init(const int* __restrict__ ew) {
    int i = blockIdx.x * blockDim.x + threadIdx.x;
    if (i < NN) g_deg[i] = 0;
    if (i < FH) { g_sum1[i] = 0.f; g_sq1[i] = 0.f; }
    if (i < 2)  { g_sum2[i] = 0.f; g_sq2[i] = 0.f; }
    if (i == 0) {
        // If edge_index is int64 (little-endian), the high 32-bit words of the
        // first 32 entries are all zero (values < 100000). For int32 layout
        // those words are random edge ids -> essentially never all zero.
        int z = 0;
        for (int e = 0; e < 32; e++) z |= ew[2 * e + 1];
        g_is64 = (z == 0) ? 1 : 0;
    }
}

// ---------------- degree (incl. self-loop added later as +1) ----------------
__global__ void k_degree(const int* __restrict__ ew) {
    int is64 = g_is64;
    int stride = gridDim.x * blockDim.x;
    for (int e = blockIdx.x * blockDim.x + threadIdx.x; e < NE; e += stride) {
        int d = is64 ? ew[2 * ((size_t)NE + e)] : ew[(size_t)NE + e];
        atomicAdd(&g_deg[d], 1);
    }
}

__global__ void k_dinv() {
    int i = blockIdx.x * blockDim.x + threadIdx.x;
    if (i < NN) g_dinv[i] = rsqrtf((float)(g_deg[i] + 1));
}

// ---------------- GEMM1: h1 = [u_Y | X] @ W1 ; agg1 init = h1 * dinv^2 ----------------
// block: 128 threads (one output column each), 32 nodes per block. 3125 blocks.
__global__ void k_gemm1(const float* __restrict__ X, const float* __restrict__ uY,
                        const float* __restrict__ W1) {
    __shared__ float sl[32][FI + 8];
    __shared__ float sdi[32];
    int n0  = blockIdx.x * 32;
    int tid = threadIdx.x;

    for (int idx = tid; idx < 32 * FI; idx += 128) {
        int n = idx / FI, k = idx % FI;
        size_t node = (size_t)(n0 + n);
        float v = (k < 64) ? uY[node * 64 + k] : X[node * 128 + (k - 64)];
        sl[n][k] = v;
    }
    if (tid < 32) sdi[tid] = g_dinv[n0 + tid];
    __syncthreads();

    int j = tid;
    float acc[32];
#pragma unroll
    for (int n = 0; n < 32; n++) acc[n] = 0.f;

    for (int k = 0; k < FI; k++) {
        float w = W1[(size_t)k * FH + j];
#pragma unroll
        for (int n = 0; n < 32; n++) acc[n] = fmaf(sl[n][k], w, acc[n]);
    }

#pragma unroll
    for (int n = 0; n < 32; n++) {
        size_t node = (size_t)(n0 + n);
        float v  = acc[n];
        float di = sdi[n];
        g_h1  [node * FH + j] = v;
        g_agg1[node * FH + j] = v * di * di;   // self-loop term
    }
}

// ---------------- edge aggregation layer 1: warp per edge, red.v4 ----------------
__global__ void k_agg1(const int* __restrict__ ew) {
    int gtid  = blockIdx.x * blockDim.x + threadIdx.x;
    int lane  = threadIdx.x & 31;
    int wid   = gtid >> 5;
    int nwarp = (gridDim.x * blockDim.x) >> 5;
    int is64  = g_is64;

    for (int e = wid; e < NE; e += nwarp) {
        int s = 0, d = 0;
        float c = 0.f;
        if (lane == 0) {
            if (is64) { s = ew[2 * (size_t)e];  d = ew[2 * ((size_t)NE + e)]; }
            else      { s = ew[(size_t)e];      d = ew[(size_t)NE + e]; }
            c = g_dinv[s] * g_dinv[d];
        }
        s = __shfl_sync(0xffffffffu, s, 0);
        d = __shfl_sync(0xffffffffu, d, 0);
        c = __shfl_sync(0xffffffffu, c, 0);

        float4 h = *((const float4*)(g_h1 + (size_t)s * FH) + lane);
        float* ap = g_agg1 + (size_t)d * FH + lane * 4;
        asm volatile("red.global.add.v4.f32 [%0], {%1,%2,%3,%4};"
                     :: "l"(ap), "f"(h.x * c), "f"(h.y * c), "f"(h.z * c), "f"(h.w * c)
                     : "memory");
    }
}

// ---------------- BN1 statistics ----------------
#define BN1_NPB 512
__global__ void k_bn1_stats() {
    int j  = threadIdx.x;            // 0..127
    int n0 = blockIdx.x * BN1_NPB;
    int n1 = n0 + BN1_NPB; if (n1 > NN) n1 = NN;
    float s = 0.f, q = 0.f;
    for (int n = n0; n < n1; n++) {
        float v = g_agg1[(size_t)n * FH + j];
        s += v;
        q = fmaf(v, v, q);
    }
    atomicAdd(&g_sum1[j], s);
    atomicAdd(&g_sq1[j], q);
}

__global__ void k_bn1_final(const float* __restrict__ gamma1, const float* __restrict__ beta1) {
    int j = threadIdx.x;
    float mean = g_sum1[j] * (1.f / NN);
    float var  = g_sq1[j] * (1.f / NN) - mean * mean;
    float sc   = gamma1[j] * rsqrtf(var + BN_EPS);
    g_scale1[j] = sc;
    g_shift1[j] = beta1[j] - mean * sc;
}

// ---------------- BN1 apply + ReLU + GEMM2 + agg2 self-init ----------------
// warp per node; lane handles 4 consecutive features.
__global__ void k_layer2(const float* __restrict__ W2) {
    int gtid  = blockIdx.x * blockDim.x + threadIdx.x;
    int lane  = threadIdx.x & 31;
    int wid   = gtid >> 5;
    int nwarp = (gridDim.x * blockDim.x) >> 5;

    float4 sc = ((const float4*)g_scale1)[lane];
    float4 sh = ((const float4*)g_shift1)[lane];
    // W2 rows f..f+3 (f = lane*4): 8 floats = two float4s
    const float4* w4 = (const float4*)W2;
    float4 wA = w4[lane * 2];        // {W2[f][0],W2[f][1],W2[f+1][0],W2[f+1][1]}
    float4 wB = w4[lane * 2 + 1];    // {W2[f+2][0],W2[f+2][1],W2[f+3][0],W2[f+3][1]}

    for (int node = wid; node < NN; node += nwarp) {
        float4 x = *((const float4*)(g_agg1 + (size_t)node * FH) + lane);
        float y0 = fmaxf(fmaf(x.x, sc.x, sh.x), 0.f);
        float y1 = fmaxf(fmaf(x.y, sc.y, sh.y), 0.f);
        float y2 = fmaxf(fmaf(x.z, sc.z, sh.z), 0.f);
        float y3 = fmaxf(fmaf(x.w, sc.w, sh.w), 0.f);
        float p0 = y0 * wA.x + y1 * wA.z + y2 * wB.x + y3 * wB.z;
        float p1 = y0 * wA.y + y1 * wA.w + y2 * wB.y + y3 * wB.w;
#pragma unroll
        for (int o = 16; o; o >>= 1) {
            p0 += __shfl_xor_sync(0xffffffffu, p0, o);
            p1 += __shfl_xor_sync(0xffffffffu, p1, o);
        }
        if (lane == 0) {
            float di = g_dinv[node];
            float dd = di * di;
            g_h2  [(size_t)node * 2 + 0] = p0;
            g_h2  [(size_t)node * 2 + 1] = p1;
            g_agg2[(size_t)node * 2 + 0] = p0 * dd;   // self-loop
            g_agg2[(size_t)node * 2 + 1] = p1 * dd;
        }
    }
}

// ---------------- edge aggregation layer 2: thread per edge, red.v2 ----------------
__global__ void k_agg2(const int* __restrict__ ew) {
    int is64   = g_is64;
    int stride = gridDim.x * blockDim.x;
    for (int e = blockIdx.x * blockDim.x + threadIdx.x; e < NE; e += stride) {
        int s, d;
        if (is64) { s = ew[2 * (size_t)e];  d = ew[2 * ((size_t)NE + e)]; }
        else      { s = ew[(size_t)e];      d = ew[(size_t)NE + e]; }
        float c  = g_dinv[s] * g_dinv[d];
        float2 h = *(const float2*)(g_h2 + (size_t)s * 2);
        float* ap = g_agg2 + (size_t)d * 2;
        asm volatile("red.global.add.v2.f32 [%0], {%1,%2};"
                     :: "l"(ap), "f"(h.x * c), "f"(h.y * c)
                     : "memory");
    }
}

// ---------------- BN2 statistics ----------------
__global__ void k_bn2_stats() {
    int gtid   = blockIdx.x * blockDim.x + threadIdx.x;
    int lane   = threadIdx.x & 31;
    int stride = gridDim.x * blockDim.x;
    float s0 = 0.f, q0 = 0.f, s1 = 0.f, q1 = 0.f;
    for (int n = gtid; n < NN; n += stride) {
        float2 a = *(const float2*)(g_agg2 + (size_t)n * 2);
        s0 += a.x; q0 = fmaf(a.x, a.x, q0);
        s1 += a.y; q1 = fmaf(a.y, a.y, q1);
    }
#pragma unroll
    for (int o = 16; o; o >>= 1) {
        s0 += __shfl_xor_sync(0xffffffffu, s0, o);
        q0 += __shfl_xor_sync(0xffffffffu, q0, o);
        s1 += __shfl_xor_sync(0xffffffffu, s1, o);
        q1 += __shfl_xor_sync(0xffffffffu, q1, o);
    }
    if (lane == 0) {
        atomicAdd(&g_sum2[0], s0); atomicAdd(&g_sq2[0], q0);
        atomicAdd(&g_sum2[1], s1); atomicAdd(&g_sq2[1], q1);
    }
}

// ---------------- BN2 + softmax ----------------
__global__ void k_out(const float* __restrict__ gamma2, const float* __restrict__ beta2,
                      float* __restrict__ out) {
    int i = blockIdx.x * blockDim.x + threadIdx.x;
    if (i >= NN) return;
    float m0 = g_sum2[0] * (1.f / NN);
    float v0 = g_sq2[0] * (1.f / NN) - m0 * m0;
    float m1 = g_sum2[1] * (1.f / NN);
    float v1 = g_sq2[1] * (1.f / NN) - m1 * m1;
    float sc0 = gamma2[0] * rsqrtf(v0 + BN_EPS);
    float sc1 = gamma2[1] * rsqrtf(v1 + BN_EPS);
    float sh0 = beta2[0] - m0 * sc0;
    float sh1 = beta2[1] - m1 * sc1;

    float2 a = *(const float2*)(g_agg2 + (size_t)i * 2);
    float y0 = fmaf(a.x, sc0, sh0);
    float y1 = fmaf(a.y, sc1, sh1);
    float mm = fmaxf(y0, y1);
    float e0 = expf(y0 - mm);
    float e1 = expf(y1 - mm);
    float inv = 1.f / (e0 + e1);
    ((float2*)out)[i] = make_float2(e0 * inv, e1 * inv);
}

// ---------------- launch ----------------
extern "C" void kernel_launch(void* const* d_in, const int* in_sizes, int n_in,
                              void* d_out, int out_size) {
    const int*   ew     = (const int*)  d_in[0];   // edge_index (int32 or int64, detected)
    const float* X      = (const float*)d_in[1];
    const float* uY     = (const float*)d_in[2];
    const float* W1     = (const float*)d_in[3];
    // d_in[4] = b1 (cancels under BatchNorm)
    const float* W2     = (const float*)d_in[5];
    // d_in[6] = b2 (cancels under BatchNorm)
    const float* gamma1 = (const float*)d_in[7];
    const float* beta1  = (const float*)d_in[8];
    const float* gamma2 = (const float*)d_in[9];
    const float* beta2  = (const float*)d_in[10];
    float* out = (float*)d_out;

    k_init   <<<(NN + 255) / 256, 256>>>(ew);
    k_degree <<<1024, 256>>>(ew);
    k_dinv   <<<(NN + 255) / 256, 256>>>();
    k_gemm1  <<<NN / 32, 128>>>(X, uY, W1);
    k_agg1   <<<4096, 256>>>(ew);
    k_bn1_stats <<<(NN + BN1_NPB - 1) / BN1_NPB, 128>>>();
    k_bn1_final <<<1, 128>>>(gamma1, beta1);
    k_layer2 <<<2048, 256>>>(W2);
    k_agg2   <<<2048, 256>>>(ew);
    k_bn2_stats <<<256, 256>>>();
    k_out    <<<(NN + 255) / 256, 256>>>(gamma2, beta2, out);
}

// round 5
// speedup vs baseline: 1.5126x; 1.5126x over previous
#include <cuda_runtime.h>
#include <math.h>

// Problem constants (fixed by the reference)
#define NN 100000      // nodes
#define NE 1600000     // edges
#define FI 192         // input feats (64 latent + 128 X)
#define FH 128         // hidden feats
#define BN_EPS 1e-5f

// ---------------- device scratch (no allocs allowed) ----------------
__device__ __align__(128) float g_h1  [(size_t)NN * FH];   // 51.2 MB
__device__ __align__(128) float g_agg1[(size_t)NN * FH];   // 51.2 MB
__device__ __align__(16)  float g_h2  [(size_t)NN * 2];
__device__ __align__(16)  float g_agg2[(size_t)NN * 2];
__device__ float g_dinv[NN];
__device__ int   g_deg [NN];
__device__ int   g_rowptr[NN + 1];
__device__ int   g_cnt [NN];
__device__ int   g_srcx[NE];     // CSR: src node per edge, grouped by dst
__device__ float g_coef[NE];     // CSR: dinv[s]*dinv[d] per edge
__device__ int   g_bsum[128];    // scan block sums
__device__ float g_sum1[FH], g_sq1[FH];
__device__ __align__(16) float g_scale1[FH];
__device__ __align__(16) float g_shift1[FH];
__device__ float g_sum2[2], g_sq2[2];
__device__ int   g_is64;

// ---------------- init: zero accumulators + detect edge dtype ----------------
__global__ void k_init(const int* __restrict__ ew) {
    int i = blockIdx.x * blockDim.x + threadIdx.x;
    if (i < NN) g_deg[i] = 0;
    if (i < FH) { g_sum1[i] = 0.f; g_sq1[i] = 0.f; }
    if (i < 2)  { g_sum2[i] = 0.f; g_sq2[i] = 0.f; }
    if (i == 0) {
        // int64 little-endian => high words of first 32 entries all zero.
        int z = 0;
        for (int e = 0; e < 32; e++) z |= ew[2 * e + 1];
        g_is64 = (z == 0) ? 1 : 0;
    }
}

// ---------------- degree histogram by dst ----------------
__global__ void k_degree(const int* __restrict__ ew) {
    int is64 = g_is64;
    int stride = gridDim.x * blockDim.x;
    for (int e = blockIdx.x * blockDim.x + threadIdx.x; e < NE; e += stride) {
        int d = is64 ? ew[2 * ((size_t)NE + e)] : ew[(size_t)NE + e];
        atomicAdd(&g_deg[d], 1);
    }
}

__global__ void k_dinv() {
    int i = blockIdx.x * blockDim.x + threadIdx.x;
    if (i < NN) g_dinv[i] = rsqrtf((float)(g_deg[i] + 1));
}

// ---------------- exclusive scan of g_deg -> g_rowptr (3 phases) ----------------
__global__ void k_scan1() {   // 98 blocks x 1024
    __shared__ int s[1024];
    int tid = threadIdx.x;
    int i = blockIdx.x * 1024 + tid;
    int v = (i < NN) ? g_deg[i] : 0;
    s[tid] = v;
    __syncthreads();
#pragma unroll
    for (int o = 1; o < 1024; o <<= 1) {
        int t = (tid >= o) ? s[tid - o] : 0;
        __syncthreads();
        s[tid] += t;
        __syncthreads();
    }
    if (i < NN) g_rowptr[i] = s[tid] - v;          // exclusive within block
    if (tid == 1023) g_bsum[blockIdx.x] = s[1023]; // block total
}

__global__ void k_scan2(int nblocks) {  // 1 thread serial scan of block sums
    if (threadIdx.x == 0 && blockIdx.x == 0) {
        int run = 0;
        for (int b = 0; b < nblocks; b++) { int t = g_bsum[b]; g_bsum[b] = run; run += t; }
    }
}

__global__ void k_scan3() {
    int i = blockIdx.x * blockDim.x + threadIdx.x;
    if (i < NN) {
        g_rowptr[i] += g_bsum[i >> 10];
        g_cnt[i] = 0;
    }
    if (i == 0) g_rowptr[NN] = NE;
}

// ---------------- scatter edges into CSR (by dst), with coefficient ----------------
__global__ void k_scatter(const int* __restrict__ ew) {
    int is64 = g_is64;
    int stride = gridDim.x * blockDim.x;
    for (int e = blockIdx.x * blockDim.x + threadIdx.x; e < NE; e += stride) {
        int s, d;
        if (is64) { s = ew[2 * (size_t)e];  d = ew[2 * ((size_t)NE + e)]; }
        else      { s = ew[(size_t)e];      d = ew[(size_t)NE + e]; }
        int pos = g_rowptr[d] + atomicAdd(&g_cnt[d], 1);
        g_srcx[pos] = s;
        g_coef[pos] = g_dinv[s] * g_dinv[d];
    }
}

// ---------------- GEMM1: h1 = [u_Y | X] @ W1 (register-tiled SGEMM) ----------------
// BM=128 nodes, BN=128 cols (full), BK=16. 256 threads, 8x8 outputs/thread.
#define GBM 128
#define GBK 16
__global__ __launch_bounds__(256, 2)
void k_gemm1(const float* __restrict__ X, const float* __restrict__ uY,
             const float* __restrict__ W1) {
    __shared__ float sA[GBK][GBM + 4];   // transposed: sA[k][node]
    __shared__ float sB[GBK][FH];        // sB[k][col]
    int tid = threadIdx.x;
    int n0  = blockIdx.x * GBM;
    int tx  = tid & 15;    // col group  (cols tx*8 .. +7)
    int ty  = tid >> 4;    // row group  (nodes ty*8 .. +7)

    float acc[8][8];
#pragma unroll
    for (int m = 0; m < 8; m++)
#pragma unroll
        for (int n = 0; n < 8; n++) acc[m][n] = 0.f;

    for (int kc = 0; kc < FI; kc += GBK) {
        // load A tile (128 nodes x 16 k) = 512 float4, 2 per thread, transpose into sA
#pragma unroll
        for (int r = 0; r < 2; r++) {
            int idx  = tid + r * 256;
            int node = idx >> 2;
            int k4   = idx & 3;
            int gn   = n0 + node;
            int gnc  = gn < NN ? gn : NN - 1;
            int k    = kc + k4 * 4;
            float4 v;
            if (k < 64) v = *(const float4*)(uY + (size_t)gnc * 64 + k);
            else        v = *(const float4*)(X  + (size_t)gnc * 128 + (k - 64));
            sA[k4 * 4 + 0][node] = v.x;
            sA[k4 * 4 + 1][node] = v.y;
            sA[k4 * 4 + 2][node] = v.z;
            sA[k4 * 4 + 3][node] = v.w;
        }
        // load B tile (16 k x 128 cols) = 512 float4, 2 per thread
#pragma unroll
        for (int r = 0; r < 2; r++) {
            int idx = tid + r * 256;
            int k   = idx >> 5;
            int c4  = idx & 31;
            *(float4*)&sB[k][c4 * 4] = *(const float4*)(W1 + (size_t)(kc + k) * FH + c4 * 4);
        }
        __syncthreads();

#pragma unroll
        for (int k = 0; k < GBK; k++) {
            float a[8], b[8];
            *(float4*)&a[0] = *(const float4*)&sA[k][ty * 8];
            *(float4*)&a[4] = *(const float4*)&sA[k][ty * 8 + 4];
            *(float4*)&b[0] = *(const float4*)&sB[k][tx * 8];
            *(float4*)&b[4] = *(const float4*)&sB[k][tx * 8 + 4];
#pragma unroll
            for (int m = 0; m < 8; m++)
#pragma unroll
                for (int n = 0; n < 8; n++)
                    acc[m][n] = fmaf(a[m], b[n], acc[m][n]);
        }
        __syncthreads();
    }

    // epilogue: h1 = acc; agg1 = acc * dinv^2 (self-loop term)
#pragma unroll
    for (int m = 0; m < 8; m++) {
        int node = n0 + ty * 8 + m;
        if (node < NN) {
            float di = g_dinv[node];
            float dd = di * di;
            size_t base = (size_t)node * FH + tx * 8;
            float4 h0 = make_float4(acc[m][0], acc[m][1], acc[m][2], acc[m][3]);
            float4 h1v = make_float4(acc[m][4], acc[m][5], acc[m][6], acc[m][7]);
            *(float4*)(g_h1 + base)     = h0;
            *(float4*)(g_h1 + base + 4) = h1v;
            float4 a0 = make_float4(h0.x * dd, h0.y * dd, h0.z * dd, h0.w * dd);
            float4 a1 = make_float4(h1v.x * dd, h1v.y * dd, h1v.z * dd, h1v.w * dd);
            *(float4*)(g_agg1 + base)     = a0;
            *(float4*)(g_agg1 + base + 4) = a1;
        }
    }
}

// ---------------- layer-1 aggregation: CSR gather, warp per dst row ----------------
__global__ void k_agg1() {
    int gtid  = blockIdx.x * blockDim.x + threadIdx.x;
    int lane  = threadIdx.x & 31;
    int wid   = gtid >> 5;
    int nwarp = (gridDim.x * blockDim.x) >> 5;

    for (int row = wid; row < NN; row += nwarp) {
        int start = g_rowptr[row];
        int end   = g_rowptr[row + 1];
        float di  = g_dinv[row];
        float dd  = di * di;
        float4 a  = ((const float4*)(g_h1 + (size_t)row * FH))[lane];
        float4 acc = make_float4(a.x * dd, a.y * dd, a.z * dd, a.w * dd);

        int i = start;
        for (; i + 2 <= end; i += 2) {
            int   s0 = g_srcx[i],     s1 = g_srcx[i + 1];
            float c0 = g_coef[i],     c1 = g_coef[i + 1];
            float4 h0 = ((const float4*)(g_h1 + (size_t)s0 * FH))[lane];
            float4 h1v = ((const float4*)(g_h1 + (size_t)s1 * FH))[lane];
            acc.x = fmaf(h0.x, c0, fmaf(h1v.x, c1, acc.x));
            acc.y = fmaf(h0.y, c0, fmaf(h1v.y, c1, acc.y));
            acc.z = fmaf(h0.z, c0, fmaf(h1v.z, c1, acc.z));
            acc.w = fmaf(h0.w, c0, fmaf(h1v.w, c1, acc.w));
        }
        if (i < end) {
            int   s0 = g_srcx[i];
            float c0 = g_coef[i];
            float4 h0 = ((const float4*)(g_h1 + (size_t)s0 * FH))[lane];
            acc.x = fmaf(h0.x, c0, acc.x);
            acc.y = fmaf(h0.y, c0, acc.y);
            acc.z = fmaf(h0.z, c0, acc.z);
            acc.w = fmaf(h0.w, c0, acc.w);
        }
        ((float4*)(g_agg1 + (size_t)row * FH))[lane] = acc;
    }
}

// ---------------- BN1 statistics ----------------
#define BN1_NPB 128
__global__ void k_bn1_stats() {
    int j  = threadIdx.x;            // 0..127 feature
    int n0 = blockIdx.x * BN1_NPB;
    int n1 = n0 + BN1_NPB; if (n1 > NN) n1 = NN;
    float s = 0.f, q = 0.f;
    for (int n = n0; n < n1; n++) {
        float v = g_agg1[(size_t)n * FH + j];
        s += v;
        q = fmaf(v, v, q);
    }
    atomicAdd(&g_sum1[j], s);
    atomicAdd(&g_sq1[j], q);
}

__global__ void k_bn1_final(const float* __restrict__ gamma1, const float* __restrict__ beta1) {
    int j = threadIdx.x;
    float mean = g_sum1[j] * (1.f / NN);
    float var  = g_sq1[j] * (1.f / NN) - mean * mean;
    float sc   = gamma1[j] * rsqrtf(var + BN_EPS);
    g_scale1[j] = sc;
    g_shift1[j] = beta1[j] - mean * sc;
}

// ---------------- BN1 apply + ReLU + GEMM2 -> h2 ----------------
__global__ void k_layer2(const float* __restrict__ W2) {
    int gtid  = blockIdx.x * blockDim.x + threadIdx.x;
    int lane  = threadIdx.x & 31;
    int wid   = gtid >> 5;
    int nwarp = (gridDim.x * blockDim.x) >> 5;

    float4 sc = ((const float4*)g_scale1)[lane];
    float4 sh = ((const float4*)g_shift1)[lane];
    const float4* w4 = (const float4*)W2;
    float4 wA = w4[lane * 2];
    float4 wB = w4[lane * 2 + 1];

    for (int node = wid; node < NN; node += nwarp) {
        float4 x = *((const float4*)(g_agg1 + (size_t)node * FH) + lane);
        float y0 = fmaxf(fmaf(x.x, sc.x, sh.x), 0.f);
        float y1 = fmaxf(fmaf(x.y, sc.y, sh.y), 0.f);
        float y2 = fmaxf(fmaf(x.z, sc.z, sh.z), 0.f);
        float y3 = fmaxf(fmaf(x.w, sc.w, sh.w), 0.f);
        float p0 = y0 * wA.x + y1 * wA.z + y2 * wB.x + y3 * wB.z;
        float p1 = y0 * wA.y + y1 * wA.w + y2 * wB.y + y3 * wB.w;
#pragma unroll
        for (int o = 16; o; o >>= 1) {
            p0 += __shfl_xor_sync(0xffffffffu, p0, o);
            p1 += __shfl_xor_sync(0xffffffffu, p1, o);
        }
        if (lane == 0) {
            g_h2[(size_t)node * 2 + 0] = p0;
            g_h2[(size_t)node * 2 + 1] = p1;
        }
    }
}

// ---------------- layer-2 aggregation: CSR gather, thread per dst row ----------------
__global__ void k_agg2() {
    int stride = gridDim.x * blockDim.x;
    for (int row = blockIdx.x * blockDim.x + threadIdx.x; row < NN; row += stride) {
        int start = g_rowptr[row];
        int end   = g_rowptr[row + 1];
        float di  = g_dinv[row];
        float dd  = di * di;
        float2 h  = *(const float2*)(g_h2 + (size_t)row * 2);
        float a0 = h.x * dd, a1 = h.y * dd;
        for (int i = start; i < end; i++) {
            int   s = g_srcx[i];
            float c = g_coef[i];
            float2 hs = *(const float2*)(g_h2 + (size_t)s * 2);
            a0 = fmaf(hs.x, c, a0);
            a1 = fmaf(hs.y, c, a1);
        }
        g_agg2[(size_t)row * 2 + 0] = a0;
        g_agg2[(size_t)row * 2 + 1] = a1;
    }
}

// ---------------- BN2 statistics ----------------
__global__ void k_bn2_stats() {
    int gtid   = blockIdx.x * blockDim.x + threadIdx.x;
    int lane   = threadIdx.x & 31;
    int stride = gridDim.x * blockDim.x;
    float s0 = 0.f, q0 = 0.f, s1 = 0.f, q1 = 0.f;
    for (int n = gtid; n < NN; n += stride) {
        float2 a = *(const float2*)(g_agg2 + (size_t)n * 2);
        s0 += a.x; q0 = fmaf(a.x, a.x, q0);
        s1 += a.y; q1 = fmaf(a.y, a.y, q1);
    }
#pragma unroll
    for (int o = 16; o; o >>= 1) {
        s0 += __shfl_xor_sync(0xffffffffu, s0, o);
        q0 += __shfl_xor_sync(0xffffffffu, q0, o);
        s1 += __shfl_xor_sync(0xffffffffu, s1, o);
        q1 += __shfl_xor_sync(0xffffffffu, q1, o);
    }
    if (lane == 0) {
        atomicAdd(&g_sum2[0], s0); atomicAdd(&g_sq2[0], q0);
        atomicAdd(&g_sum2[1], s1); atomicAdd(&g_sq2[1], q1);
    }
}

// ---------------- BN2 + softmax ----------------
__global__ void k_out(const float* __restrict__ gamma2, const float* __restrict__ beta2,
                      float* __restrict__ out) {
    int i = blockIdx.x * blockDim.x + threadIdx.x;
    if (i >= NN) return;
    float m0 = g_sum2[0] * (1.f / NN);
    float v0 = g_sq2[0] * (1.f / NN) - m0 * m0;
    float m1 = g_sum2[1] * (1.f / NN);
    float v1 = g_sq2[1] * (1.f / NN) - m1 * m1;
    float sc0 = gamma2[0] * rsqrtf(v0 + BN_EPS);
    float sc1 = gamma2[1] * rsqrtf(v1 + BN_EPS);
    float sh0 = beta2[0] - m0 * sc0;
    float sh1 = beta2[1] - m1 * sc1;

    float2 a = *(const float2*)(g_agg2 + (size_t)i * 2);
    float y0 = fmaf(a.x, sc0, sh0);
    float y1 = fmaf(a.y, sc1, sh1);
    float mm = fmaxf(y0, y1);
    float e0 = expf(y0 - mm);
    float e1 = expf(y1 - mm);
    float inv = 1.f / (e0 + e1);
    ((float2*)out)[i] = make_float2(e0 * inv, e1 * inv);
}

// ---------------- launch ----------------
extern "C" void kernel_launch(void* const* d_in, const int* in_sizes, int n_in,
                              void* d_out, int out_size) {
    const int*   ew     = (const int*)  d_in[0];   // edge_index (int32 or int64, detected)
    const float* X      = (const float*)d_in[1];
    const float* uY     = (const float*)d_in[2];
    const float* W1     = (const float*)d_in[3];
    // d_in[4] = b1 (cancels under BatchNorm)
    const float* W2     = (const float*)d_in[5];
    // d_in[6] = b2 (cancels under BatchNorm)
    const float* gamma1 = (const float*)d_in[7];
    const float* beta1  = (const float*)d_in[8];
    const float* gamma2 = (const float*)d_in[9];
    const float* beta2  = (const float*)d_in[10];
    float* out = (float*)d_out;

    const int nscan = (NN + 1023) / 1024;   // 98

    k_init    <<<(NN + 255) / 256, 256>>>(ew);
    k_degree  <<<1024, 256>>>(ew);
    k_dinv    <<<(NN + 255) / 256, 256>>>();
    k_scan1   <<<nscan, 1024>>>();
    k_scan2   <<<1, 32>>>(nscan);
    k_scan3   <<<(NN + 255) / 256, 256>>>();
    k_scatter <<<1024, 256>>>(ew);
    k_gemm1   <<<(NN + GBM - 1) / GBM, 256>>>(X, uY, W1);
    k_agg1    <<<2048, 256>>>();
    k_bn1_stats <<<(NN + BN1_NPB - 1) / BN1_NPB, 128>>>();
    k_bn1_final <<<1, 128>>>(gamma1, beta1);
    k_layer2  <<<2048, 256>>>(W2);
    k_agg2    <<<512, 256>>>();
    k_bn2_stats <<<256, 256>>>();
    k_out     <<<(NN + 255) / 256, 256>>>(gamma2, beta2, out);
}

// round 6
// speedup vs baseline: 1.6864x; 1.1149x over previous
#include <cuda_runtime.h>
#include <cuda_fp16.h>
#include <math.h>

// Problem constants (fixed by the reference)
#define NN 100000      // nodes
#define NE 1600000     // edges
#define FI 192         // input feats (64 latent + 128 X)
#define FH 128         // hidden feats
#define BN_EPS 1e-5f

// ---------------- device scratch (no allocs allowed) ----------------
__device__ __align__(128) __half g_h1h[(size_t)NN * FH];   // 25.6 MB (fp16 gather payload)
__device__ __align__(128) float  g_agg1[(size_t)NN * FH];  // 51.2 MB
__device__ __align__(16)  float  g_h2  [(size_t)NN * 2];
__device__ __align__(16)  float  g_agg2[(size_t)NN * 2];
__device__ float g_dinv[NN];
__device__ int   g_deg [NN];
__device__ int   g_rowptr[NN + 1];
__device__ int   g_cnt [NN];
__device__ int   g_srcx[NE];     // CSR: src node per edge, grouped by dst
__device__ float g_coef[NE];     // CSR: dinv[s]*dinv[d] per edge
__device__ int   g_bsum[128];    // scan block sums
__device__ float g_sum1[FH], g_sq1[FH];
__device__ __align__(16) float g_scale1[FH];
__device__ __align__(16) float g_shift1[FH];
__device__ float g_sum2[2], g_sq2[2];
__device__ int   g_is64;

// ---------------- init: zero accumulators + detect edge dtype ----------------
__global__ void k_init(const int* __restrict__ ew) {
    int i = blockIdx.x * blockDim.x + threadIdx.x;
    if (i < NN) g_deg[i] = 0;
    if (i < FH) { g_sum1[i] = 0.f; g_sq1[i] = 0.f; }
    if (i < 2)  { g_sum2[i] = 0.f; g_sq2[i] = 0.f; }
    if (i == 0) {
        // int64 little-endian => high words of first 32 entries all zero.
        int z = 0;
        for (int e = 0; e < 32; e++) z |= ew[2 * e + 1];
        g_is64 = (z == 0) ? 1 : 0;
    }
}

// ---------------- degree histogram by dst ----------------
__global__ void k_degree(const int* __restrict__ ew) {
    int is64 = g_is64;
    int stride = gridDim.x * blockDim.x;
    for (int e = blockIdx.x * blockDim.x + threadIdx.x; e < NE; e += stride) {
        int d = is64 ? ew[2 * ((size_t)NE + e)] : ew[(size_t)NE + e];
        atomicAdd(&g_deg[d], 1);
    }
}

__global__ void k_dinv() {
    int i = blockIdx.x * blockDim.x + threadIdx.x;
    if (i < NN) g_dinv[i] = rsqrtf((float)(g_deg[i] + 1));
}

// ---------------- exclusive scan of g_deg -> g_rowptr (3 phases) ----------------
__global__ void k_scan1() {   // 98 blocks x 1024
    __shared__ int s[1024];
    int tid = threadIdx.x;
    int i = blockIdx.x * 1024 + tid;
    int v = (i < NN) ? g_deg[i] : 0;
    s[tid] = v;
    __syncthreads();
#pragma unroll
    for (int o = 1; o < 1024; o <<= 1) {
        int t = (tid >= o) ? s[tid - o] : 0;
        __syncthreads();
        s[tid] += t;
        __syncthreads();
    }
    if (i < NN) g_rowptr[i] = s[tid] - v;          // exclusive within block
    if (tid == 1023) g_bsum[blockIdx.x] = s[1023]; // block total
}

__global__ void k_scan2(int nblocks) {
    if (threadIdx.x == 0 && blockIdx.x == 0) {
        int run = 0;
        for (int b = 0; b < nblocks; b++) { int t = g_bsum[b]; g_bsum[b] = run; run += t; }
    }
}

__global__ void k_scan3() {
    int i = blockIdx.x * blockDim.x + threadIdx.x;
    if (i < NN) {
        g_rowptr[i] += g_bsum[i >> 10];
        g_cnt[i] = 0;
    }
    if (i == 0) g_rowptr[NN] = NE;
}

// ---------------- scatter edges into CSR (by dst), with coefficient ----------------
__global__ void k_scatter(const int* __restrict__ ew) {
    int is64 = g_is64;
    int stride = gridDim.x * blockDim.x;
    for (int e = blockIdx.x * blockDim.x + threadIdx.x; e < NE; e += stride) {
        int s, d;
        if (is64) { s = ew[2 * (size_t)e];  d = ew[2 * ((size_t)NE + e)]; }
        else      { s = ew[(size_t)e];      d = ew[(size_t)NE + e]; }
        int pos = g_rowptr[d] + atomicAdd(&g_cnt[d], 1);
        g_srcx[pos] = s;
        g_coef[pos] = g_dinv[s] * g_dinv[d];
    }
}

// ---------------- GEMM1: h1h = fp16([u_Y | X] @ W1), software pipelined ----------------
// BM=128 nodes, BN=128 cols (full), BK=16. 256 threads, 8x8 outputs/thread.
#define GBM 128
#define GBK 16
__global__ __launch_bounds__(256, 2)
void k_gemm1(const float* __restrict__ X, const float* __restrict__ uY,
             const float* __restrict__ W1) {
    __shared__ float sA[GBK][GBM + 4];   // transposed: sA[k][node]
    __shared__ float sB[GBK][FH];        // sB[k][col]
    int tid = threadIdx.x;
    int n0  = blockIdx.x * GBM;
    int tx  = tid & 15;    // col group  (cols tx*8 .. +7)
    int ty  = tid >> 4;    // row group  (nodes ty*8 .. +7)

    // load-index precompute (A: 2 float4 per thread; B: 2 float4 per thread)
    int aNode[2], aK4[2], bK[2], bC4[2];
#pragma unroll
    for (int r = 0; r < 2; r++) {
        int idx = tid + r * 256;
        aNode[r] = idx >> 2;  aK4[r] = idx & 3;
        bK[r]    = idx >> 5;  bC4[r] = idx & 31;
    }

    float4 pa[2], pb[2];
    // prefetch chunk 0
#pragma unroll
    for (int r = 0; r < 2; r++) {
        int gn  = n0 + aNode[r];
        int gnc = gn < NN ? gn : NN - 1;
        int k   = aK4[r] * 4;
        pa[r] = (k < 64) ? *(const float4*)(uY + (size_t)gnc * 64 + k)
                         : *(const float4*)(X  + (size_t)gnc * 128 + (k - 64));
        pb[r] = *(const float4*)(W1 + (size_t)bK[r] * FH + bC4[r] * 4);
    }

    float acc[8][8];
#pragma unroll
    for (int m = 0; m < 8; m++)
#pragma unroll
        for (int n = 0; n < 8; n++) acc[m][n] = 0.f;

    for (int kc = 0; kc < FI; kc += GBK) {
        __syncthreads();   // all reads of previous tile done
        // commit prefetched tile to smem
#pragma unroll
        for (int r = 0; r < 2; r++) {
            sA[aK4[r] * 4 + 0][aNode[r]] = pa[r].x;
            sA[aK4[r] * 4 + 1][aNode[r]] = pa[r].y;
            sA[aK4[r] * 4 + 2][aNode[r]] = pa[r].z;
            sA[aK4[r] * 4 + 3][aNode[r]] = pa[r].w;
            *(float4*)&sB[bK[r]][bC4[r] * 4] = pb[r];
        }
        __syncthreads();

        // prefetch next chunk while computing
        int kn = kc + GBK;
        if (kn < FI) {
#pragma unroll
            for (int r = 0; r < 2; r++) {
                int gn  = n0 + aNode[r];
                int gnc = gn < NN ? gn : NN - 1;
                int k   = kn + aK4[r] * 4;
                pa[r] = (k < 64) ? *(const float4*)(uY + (size_t)gnc * 64 + k)
                                 : *(const float4*)(X  + (size_t)gnc * 128 + (k - 64));
                pb[r] = *(const float4*)(W1 + (size_t)(kn + bK[r]) * FH + bC4[r] * 4);
            }
        }

#pragma unroll
        for (int k = 0; k < GBK; k++) {
            float a[8], b[8];
            *(float4*)&a[0] = *(const float4*)&sA[k][ty * 8];
            *(float4*)&a[4] = *(const float4*)&sA[k][ty * 8 + 4];
            *(float4*)&b[0] = *(const float4*)&sB[k][tx * 8];
            *(float4*)&b[4] = *(const float4*)&sB[k][tx * 8 + 4];
#pragma unroll
            for (int m = 0; m < 8; m++)
#pragma unroll
                for (int n = 0; n < 8; n++)
                    acc[m][n] = fmaf(a[m], b[n], acc[m][n]);
        }
    }

    // epilogue: h1h = fp16(acc). 8 cols per row = 16B = one float4 store.
#pragma unroll
    for (int m = 0; m < 8; m++) {
        int node = n0 + ty * 8 + m;
        if (node < NN) {
            __half2 hh[4];
            hh[0] = __floats2half2_rn(acc[m][0], acc[m][1]);
            hh[1] = __floats2half2_rn(acc[m][2], acc[m][3]);
            hh[2] = __floats2half2_rn(acc[m][4], acc[m][5]);
            hh[3] = __floats2half2_rn(acc[m][6], acc[m][7]);
            *(float4*)(g_h1h + (size_t)node * FH + tx * 8) = *(float4*)hh;
        }
    }
}

// ---------------- layer-1 aggregation: CSR gather of fp16 rows, warp per dst ----------------
// lane handles 4 features (8B = 2 half2 per row read). fp32 accumulation.
__global__ void k_agg1() {
    int gtid  = blockIdx.x * blockDim.x + threadIdx.x;
    int lane  = threadIdx.x & 31;
    int wid   = gtid >> 5;
    int nwarp = (gridDim.x * blockDim.x) >> 5;

    for (int row = wid; row < NN; row += nwarp) {
        int start = g_rowptr[row];
        int end   = g_rowptr[row + 1];
        float di  = g_dinv[row];
        float dd  = di * di;

        float a0, a1, a2, a3;
        {   // self-loop term from fp16 row
            uint2 raw = *((const uint2*)(g_h1h + (size_t)row * FH) + lane);
            float2 f0 = __half22float2(*(const __half2*)&raw.x);
            float2 f1 = __half22float2(*(const __half2*)&raw.y);
            a0 = f0.x * dd; a1 = f0.y * dd; a2 = f1.x * dd; a3 = f1.y * dd;
        }

        int i = start;
        for (; i + 2 <= end; i += 2) {
            int   s0 = g_srcx[i],     s1 = g_srcx[i + 1];
            float c0 = g_coef[i],     c1 = g_coef[i + 1];
            uint2 r0 = *((const uint2*)(g_h1h + (size_t)s0 * FH) + lane);
            uint2 r1 = *((const uint2*)(g_h1h + (size_t)s1 * FH) + lane);
            float2 f00 = __half22float2(*(const __half2*)&r0.x);
            float2 f01 = __half22float2(*(const __half2*)&r0.y);
            float2 f10 = __half22float2(*(const __half2*)&r1.x);
            float2 f11 = __half22float2(*(const __half2*)&r1.y);
            a0 = fmaf(f00.x, c0, fmaf(f10.x, c1, a0));
            a1 = fmaf(f00.y, c0, fmaf(f10.y, c1, a1));
            a2 = fmaf(f01.x, c0, fmaf(f11.x, c1, a2));
            a3 = fmaf(f01.y, c0, fmaf(f11.y, c1, a3));
        }
        if (i < end) {
            int   s0 = g_srcx[i];
            float c0 = g_coef[i];
            uint2 r0 = *((const uint2*)(g_h1h + (size_t)s0 * FH) + lane);
            float2 f00 = __half22float2(*(const __half2*)&r0.x);
            float2 f01 = __half22float2(*(const __half2*)&r0.y);
            a0 = fmaf(f00.x, c0, a0);
            a1 = fmaf(f00.y, c0, a1);
            a2 = fmaf(f01.x, c0, a2);
            a3 = fmaf(f01.y, c0, a3);
        }
        *((float4*)(g_agg1 + (size_t)row * FH) + lane) = make_float4(a0, a1, a2, a3);
    }
}

// ---------------- BN1 statistics ----------------
#define BN1_NPB 128
__global__ void k_bn1_stats() {
    int j  = threadIdx.x;            // 0..127 feature
    int n0 = blockIdx.x * BN1_NPB;
    int n1 = n0 + BN1_NPB; if (n1 > NN) n1 = NN;
    float s = 0.f, q = 0.f;
    for (int n = n0; n < n1; n++) {
        float v = g_agg1[(size_t)n * FH + j];
        s += v;
        q = fmaf(v, v, q);
    }
    atomicAdd(&g_sum1[j], s);
    atomicAdd(&g_sq1[j], q);
}

__global__ void k_bn1_final(const float* __restrict__ gamma1, const float* __restrict__ beta1) {
    int j = threadIdx.x;
    float mean = g_sum1[j] * (1.f / NN);
    float var  = g_sq1[j] * (1.f / NN) - mean * mean;
    float sc   = gamma1[j] * rsqrtf(var + BN_EPS);
    g_scale1[j] = sc;
    g_shift1[j] = beta1[j] - mean * sc;
}

// ---------------- BN1 apply + ReLU + GEMM2 -> h2 ----------------
__global__ void k_layer2(const float* __restrict__ W2) {
    int gtid  = blockIdx.x * blockDim.x + threadIdx.x;
    int lane  = threadIdx.x & 31;
    int wid   = gtid >> 5;
    int nwarp = (gridDim.x * blockDim.x) >> 5;

    float4 sc = ((const float4*)g_scale1)[lane];
    float4 sh = ((const float4*)g_shift1)[lane];
    const float4* w4 = (const float4*)W2;
    float4 wA = w4[lane * 2];
    float4 wB = w4[lane * 2 + 1];

    for (int node = wid; node < NN; node += nwarp) {
        float4 x = *((const float4*)(g_agg1 + (size_t)node * FH) + lane);
        float y0 = fmaxf(fmaf(x.x, sc.x, sh.x), 0.f);
        float y1 = fmaxf(fmaf(x.y, sc.y, sh.y), 0.f);
        float y2 = fmaxf(fmaf(x.z, sc.z, sh.z), 0.f);
        float y3 = fmaxf(fmaf(x.w, sc.w, sh.w), 0.f);
        float p0 = y0 * wA.x + y1 * wA.z + y2 * wB.x + y3 * wB.z;
        float p1 = y0 * wA.y + y1 * wA.w + y2 * wB.y + y3 * wB.w;
#pragma unroll
        for (int o = 16; o; o >>= 1) {
            p0 += __shfl_xor_sync(0xffffffffu, p0, o);
            p1 += __shfl_xor_sync(0xffffffffu, p1, o);
        }
        if (lane == 0) {
            g_h2[(size_t)node * 2 + 0] = p0;
            g_h2[(size_t)node * 2 + 1] = p1;
        }
    }
}

// ---------------- layer-2 aggregation: CSR gather, thread per dst row ----------------
__global__ void k_agg2() {
    int stride = gridDim.x * blockDim.x;
    for (int row = blockIdx.x * blockDim.x + threadIdx.x; row < NN; row += stride) {
        int start = g_rowptr[row];
        int end   = g_rowptr[row + 1];
        float di  = g_dinv[row];
        float dd  = di * di;
        float2 h  = *(const float2*)(g_h2 + (size_t)row * 2);
        float a0 = h.x * dd, a1 = h.y * dd;
        for (int i = start; i < end; i++) {
            int   s = g_srcx[i];
            float c = g_coef[i];
            float2 hs = *(const float2*)(g_h2 + (size_t)s * 2);
            a0 = fmaf(hs.x, c, a0);
            a1 = fmaf(hs.y, c, a1);
        }
        g_agg2[(size_t)row * 2 + 0] = a0;
        g_agg2[(size_t)row * 2 + 1] = a1;
    }
}

// ---------------- BN2 statistics ----------------
__global__ void k_bn2_stats() {
    int gtid   = blockIdx.x * blockDim.x + threadIdx.x;
    int lane   = threadIdx.x & 31;
    int stride = gridDim.x * blockDim.x;
    float s0 = 0.f, q0 = 0.f, s1 = 0.f, q1 = 0.f;
    for (int n = gtid; n < NN; n += stride) {
        float2 a = *(const float2*)(g_agg2 + (size_t)n * 2);
        s0 += a.x; q0 = fmaf(a.x, a.x, q0);
        s1 += a.y; q1 = fmaf(a.y, a.y, q1);
    }
#pragma unroll
    for (int o = 16; o; o >>= 1) {
        s0 += __shfl_xor_sync(0xffffffffu, s0, o);
        q0 += __shfl_xor_sync(0xffffffffu, q0, o);
        s1 += __shfl_xor_sync(0xffffffffu, s1, o);
        q1 += __shfl_xor_sync(0xffffffffu, q1, o);
    }
    if (lane == 0) {
        atomicAdd(&g_sum2[0], s0); atomicAdd(&g_sq2[0], q0);
        atomicAdd(&g_sum2[1], s1); atomicAdd(&g_sq2[1], q1);
    }
}

// ---------------- BN2 + softmax ----------------
__global__ void k_out(const float* __restrict__ gamma2, const float* __restrict__ beta2,
                      float* __restrict__ out) {
    int i = blockIdx.x * blockDim.x + threadIdx.x;
    if (i >= NN) return;
    float m0 = g_sum2[0] * (1.f / NN);
    float v0 = g_sq2[0] * (1.f / NN) - m0 * m0;
    float m1 = g_sum2[1] * (1.f / NN);
    float v1 = g_sq2[1] * (1.f / NN) - m1 * m1;
    float sc0 = gamma2[0] * rsqrtf(v0 + BN_EPS);
    float sc1 = gamma2[1] * rsqrtf(v1 + BN_EPS);
    float sh0 = beta2[0] - m0 * sc0;
    float sh1 = beta2[1] - m1 * sc1;

    float2 a = *(const float2*)(g_agg2 + (size_t)i * 2);
    float y0 = fmaf(a.x, sc0, sh0);
    float y1 = fmaf(a.y, sc1, sh1);
    float mm = fmaxf(y0, y1);
    float e0 = expf(y0 - mm);
    float e1 = expf(y1 - mm);
    float inv = 1.f / (e0 + e1);
    ((float2*)out)[i] = make_float2(e0 * inv, e1 * inv);
}

// ---------------- launch ----------------
extern "C" void kernel_launch(void* const* d_in, const int* in_sizes, int n_in,
                              void* d_out, int out_size) {
    const int*   ew     = (const int*)  d_in[0];   // edge_index (int32 or int64, detected)
    const float* X      = (const float*)d_in[1];
    const float* uY     = (const float*)d_in[2];
    const float* W1     = (const float*)d_in[3];
    // d_in[4] = b1 (cancels under BatchNorm)
    const float* W2     = (const float*)d_in[5];
    // d_in[6] = b2 (cancels under BatchNorm)
    const float* gamma1 = (const float*)d_in[7];
    const float* beta1  = (const float*)d_in[8];
    const float* gamma2 = (const float*)d_in[9];
    const float* beta2  = (const float*)d_in[10];
    float* out = (float*)d_out;

    const int nscan = (NN + 1023) / 1024;   // 98

    k_init    <<<(NN + 255) / 256, 256>>>(ew);
    k_degree  <<<1024, 256>>>(ew);
    k_dinv    <<<(NN + 255) / 256, 256>>>();
    k_scan1   <<<nscan, 1024>>>();
    k_scan2   <<<1, 32>>>(nscan);
    k_scan3   <<<(NN + 255) / 256, 256>>>();
    k_scatter <<<1024, 256>>>(ew);
    k_gemm1   <<<(NN + GBM - 1) / GBM, 256>>>(X, uY, W1);
    k_agg1    <<<2048, 256>>>();
    k_bn1_stats <<<(NN + BN1_NPB - 1) / BN1_NPB, 128>>>();
    k_bn1_final <<<1, 128>>>(gamma1, beta1);
    k_layer2  <<<2048, 256>>>(W2);
    k_agg2    <<<512, 256>>>();
    k_bn2_stats <<<256, 256>>>();
    k_out     <<<(NN + 255) / 256, 256>>>(gamma2, beta2, out);
}

// round 7
// speedup vs baseline: 2.3875x; 1.4157x over previous
#include <cuda_runtime.h>
#include <cuda_fp16.h>
#include <math.h>

// Problem constants (fixed by the reference)
#define NN 100000      // nodes
#define NE 1600000     // edges
#define FI 192         // input feats (64 latent + 128 X)
#define FH 128         // hidden feats
#define BN_EPS 1e-5f

// ---------------- device scratch (no allocs allowed) ----------------
__device__ __align__(128) __half g_h1h[(size_t)NN * FH];   // 25.6 MB (fp16 gather payload)
__device__ __align__(128) float  g_agg1[(size_t)NN * FH];  // 51.2 MB
__device__ __align__(16)  float  g_h2  [(size_t)NN * 2];
__device__ __align__(16)  float  g_agg2[(size_t)NN * 2];
__device__ float g_dinv[NN];
__device__ int   g_deg [NN];
__device__ int   g_rowptr[NN + 1];
__device__ int   g_cnt [NN];
__device__ int   g_srcx[NE];     // CSR: src node per edge, grouped by dst
__device__ float g_coef[NE];     // CSR: dinv[s]*dinv[d] per edge
__device__ int   g_bsum[128];    // scan block sums
__device__ float g_sum1[FH], g_sq1[FH];
__device__ __align__(16) float g_scale1[FH];
__device__ __align__(16) float g_shift1[FH];
__device__ float g_sum2[2], g_sq2[2];
__device__ int   g_is64;

// ---------------- mma helpers ----------------
__device__ __forceinline__ void ldsm_x4(unsigned* r, const void* p) {
    unsigned a = (unsigned)__cvta_generic_to_shared(p);
    asm volatile("ldmatrix.sync.aligned.m8n8.x4.shared.b16 {%0,%1,%2,%3}, [%4];"
                 : "=r"(r[0]), "=r"(r[1]), "=r"(r[2]), "=r"(r[3]) : "r"(a));
}
__device__ __forceinline__ void ldsm_x4_t(unsigned* r, const void* p) {
    unsigned a = (unsigned)__cvta_generic_to_shared(p);
    asm volatile("ldmatrix.sync.aligned.m8n8.x4.trans.shared.b16 {%0,%1,%2,%3}, [%4];"
                 : "=r"(r[0]), "=r"(r[1]), "=r"(r[2]), "=r"(r[3]) : "r"(a));
}
__device__ __forceinline__ void mma16816(float* c, const unsigned* a, const unsigned* b) {
    asm volatile("mma.sync.aligned.m16n8k16.row.col.f32.f16.f16.f32 "
                 "{%0,%1,%2,%3}, {%4,%5,%6,%7}, {%8,%9}, {%0,%1,%2,%3};"
                 : "+f"(c[0]), "+f"(c[1]), "+f"(c[2]), "+f"(c[3])
                 : "r"(a[0]), "r"(a[1]), "r"(a[2]), "r"(a[3]), "r"(b[0]), "r"(b[1]));
}

// ---------------- init: zero accumulators + detect edge dtype ----------------
__global__ void k_init(const int* __restrict__ ew) {
    int i = blockIdx.x * blockDim.x + threadIdx.x;
    if (i < NN) g_deg[i] = 0;
    if (i < FH) { g_sum1[i] = 0.f; g_sq1[i] = 0.f; }
    if (i < 2)  { g_sum2[i] = 0.f; g_sq2[i] = 0.f; }
    if (i == 0) {
        // int64 little-endian => high words of first 32 entries all zero.
        int z = 0;
        for (int e = 0; e < 32; e++) z |= ew[2 * e + 1];
        g_is64 = (z == 0) ? 1 : 0;
    }
}

// ---------------- degree histogram by dst ----------------
__global__ void k_degree(const int* __restrict__ ew) {
    int is64 = g_is64;
    int stride = gridDim.x * blockDim.x;
    for (int e = blockIdx.x * blockDim.x + threadIdx.x; e < NE; e += stride) {
        int d = is64 ? ew[2 * ((size_t)NE + e)] : ew[(size_t)NE + e];
        atomicAdd(&g_deg[d], 1);
    }
}

// ---------------- scan phase 1 (+ fused dinv) ----------------
__global__ void k_scan1() {   // 98 blocks x 1024
    __shared__ int s[1024];
    int tid = threadIdx.x;
    int i = blockIdx.x * 1024 + tid;
    int v = 0;
    if (i < NN) {
        v = g_deg[i];
        g_dinv[i] = rsqrtf((float)(v + 1));
    }
    s[tid] = v;
    __syncthreads();
#pragma unroll
    for (int o = 1; o < 1024; o <<= 1) {
        int t = (tid >= o) ? s[tid - o] : 0;
        __syncthreads();
        s[tid] += t;
        __syncthreads();
    }
    if (i < NN) g_rowptr[i] = s[tid] - v;          // exclusive within block
    if (tid == 1023) g_bsum[blockIdx.x] = s[1023]; // block total
}

__global__ void k_scan2(int nblocks) {   // 1 block x 128, shared scan
    __shared__ int s[128];
    int t = threadIdx.x;
    int v = (t < nblocks) ? g_bsum[t] : 0;
    s[t] = v;
    __syncthreads();
#pragma unroll
    for (int o = 1; o < 128; o <<= 1) {
        int x = (t >= o) ? s[t - o] : 0;
        __syncthreads();
        s[t] += x;
        __syncthreads();
    }
    if (t < nblocks) g_bsum[t] = s[t] - v;   // exclusive
}

__global__ void k_scan3() {
    int i = blockIdx.x * blockDim.x + threadIdx.x;
    if (i < NN) {
        g_rowptr[i] += g_bsum[i >> 10];
        g_cnt[i] = 0;
    }
    if (i == 0) g_rowptr[NN] = NE;
}

// ---------------- scatter edges into CSR (by dst), with coefficient ----------------
__global__ void k_scatter(const int* __restrict__ ew) {
    int is64 = g_is64;
    int stride = gridDim.x * blockDim.x;
    for (int e = blockIdx.x * blockDim.x + threadIdx.x; e < NE; e += stride) {
        int s, d;
        if (is64) { s = ew[2 * (size_t)e];  d = ew[2 * ((size_t)NE + e)]; }
        else      { s = ew[(size_t)e];      d = ew[(size_t)NE + e]; }
        int pos = g_rowptr[d] + atomicAdd(&g_cnt[d], 1);
        g_srcx[pos] = s;
        g_coef[pos] = g_dinv[s] * g_dinv[d];
    }
}

// ---------------- GEMM1 (tensor cores): h1h = fp16([u_Y | X] @ W1) ----------------
// Tile M=128 x N=128(full), K-step 32. 256 threads = 8 warps (4 warp_m x 2 warp_n).
// Warp tile 32x64: 2 m16-frags x 8 n8-frags, mma.m16n8k16 fp16 in / fp32 acc.
#define SA_LD 40     // 32 + 8 halves padding
#define SB_LD 136    // 128 + 8 halves padding
__global__ __launch_bounds__(256, 2)
void k_gemm1(const float* __restrict__ X, const float* __restrict__ uY,
             const float* __restrict__ W1) {
    __shared__ __half sA[128][SA_LD];
    __shared__ __half sB[32][SB_LD];
    int tid   = threadIdx.x;
    int lane  = tid & 31;
    int wid   = tid >> 5;
    int warp_m = wid >> 1;          // 0..3
    int warp_n = wid & 1;           // 0..1
    int m0 = blockIdx.x * 128;

    float acc[2][8][4];
#pragma unroll
    for (int mi = 0; mi < 2; mi++)
#pragma unroll
        for (int ni = 0; ni < 8; ni++)
#pragma unroll
            for (int r = 0; r < 4; r++) acc[mi][ni][r] = 0.f;

    for (int kc = 0; kc < FI; kc += 32) {
        // stage A tile: 128 nodes x 32 k (convert fp32 -> fp16)
#pragma unroll
        for (int r = 0; r < 4; r++) {
            int idx  = tid + r * 256;      // 0..1023
            int node = idx >> 3;           // 0..127
            int kq   = idx & 7;            // 0..7 (4-wide k group)
            int gn   = m0 + node; if (gn >= NN) gn = NN - 1;
            int k    = kc + kq * 4;
            float4 v = (k < 64) ? *(const float4*)(uY + (size_t)gn * 64 + k)
                                : *(const float4*)(X  + (size_t)gn * 128 + (k - 64));
            __half2 h01 = __floats2half2_rn(v.x, v.y);
            __half2 h23 = __floats2half2_rn(v.z, v.w);
            *(__half2*)&sA[node][kq * 4]     = h01;
            *(__half2*)&sA[node][kq * 4 + 2] = h23;
        }
        // stage B tile: 32 k x 128 cols
#pragma unroll
        for (int r = 0; r < 4; r++) {
            int idx = tid + r * 256;
            int k   = idx >> 5;            // 0..31
            int nq  = idx & 31;            // 0..31 (4-wide col group)
            float4 v = *(const float4*)(W1 + (size_t)(kc + k) * FH + nq * 4);
            __half2 h01 = __floats2half2_rn(v.x, v.y);
            __half2 h23 = __floats2half2_rn(v.z, v.w);
            *(__half2*)&sB[k][nq * 4]     = h01;
            *(__half2*)&sB[k][nq * 4 + 2] = h23;
        }
        __syncthreads();

#pragma unroll
        for (int ck = 0; ck < 32; ck += 16) {
            unsigned a[2][4];
#pragma unroll
            for (int mi = 0; mi < 2; mi++) {
                int row = warp_m * 32 + mi * 16 + (lane & 15);
                int col = ck + (lane >> 4) * 8;
                ldsm_x4(a[mi], &sA[row][col]);
            }
            unsigned b[8][2];
#pragma unroll
            for (int bi = 0; bi < 4; bi++) {
                unsigned t4[4];
                int krow = ck + (lane & 15);
                int ncol = warp_n * 64 + bi * 16 + (lane >> 4) * 8;
                ldsm_x4_t(t4, &sB[krow][ncol]);
                b[2 * bi][0]     = t4[0]; b[2 * bi][1]     = t4[1];
                b[2 * bi + 1][0] = t4[2]; b[2 * bi + 1][1] = t4[3];
            }
#pragma unroll
            for (int mi = 0; mi < 2; mi++)
#pragma unroll
                for (int ni = 0; ni < 8; ni++)
                    mma16816(acc[mi][ni], a[mi], b[ni]);
        }
        __syncthreads();
    }

    // epilogue: fp16 store. c0/c1 -> (row, col..col+1), c2/c3 -> (row+8, col..col+1)
#pragma unroll
    for (int mi = 0; mi < 2; mi++) {
        int row = m0 + warp_m * 32 + mi * 16 + (lane >> 2);
#pragma unroll
        for (int ni = 0; ni < 8; ni++) {
            int col = warp_n * 64 + ni * 8 + (lane & 3) * 2;
            if (row < NN)
                *(__half2*)(g_h1h + (size_t)row * FH + col) =
                    __floats2half2_rn(acc[mi][ni][0], acc[mi][ni][1]);
            if (row + 8 < NN)
                *(__half2*)(g_h1h + (size_t)(row + 8) * FH + col) =
                    __floats2half2_rn(acc[mi][ni][2], acc[mi][ni][3]);
        }
    }
}

// ---------------- layer-1 aggregation: CSR gather of fp16 rows, warp per dst ----------------
__global__ void k_agg1() {
    int gtid  = blockIdx.x * blockDim.x + threadIdx.x;
    int lane  = threadIdx.x & 31;
    int wid   = gtid >> 5;
    int nwarp = (gridDim.x * blockDim.x) >> 5;

    for (int row = wid; row < NN; row += nwarp) {
        int start = g_rowptr[row];
        int end   = g_rowptr[row + 1];
        float di  = g_dinv[row];
        float dd  = di * di;

        float a0, a1, a2, a3;
        {   // self-loop term from fp16 row
            uint2 raw = *((const uint2*)(g_h1h + (size_t)row * FH) + lane);
            float2 f0 = __half22float2(*(const __half2*)&raw.x);
            float2 f1 = __half22float2(*(const __half2*)&raw.y);
            a0 = f0.x * dd; a1 = f0.y * dd; a2 = f1.x * dd; a3 = f1.y * dd;
        }

        int i = start;
        for (; i + 2 <= end; i += 2) {
            int   s0 = g_srcx[i],     s1 = g_srcx[i + 1];
            float c0 = g_coef[i],     c1 = g_coef[i + 1];
            uint2 r0 = *((const uint2*)(g_h1h + (size_t)s0 * FH) + lane);
            uint2 r1 = *((const uint2*)(g_h1h + (size_t)s1 * FH) + lane);
            float2 f00 = __half22float2(*(const __half2*)&r0.x);
            float2 f01 = __half22float2(*(const __half2*)&r0.y);
            float2 f10 = __half22float2(*(const __half2*)&r1.x);
            float2 f11 = __half22float2(*(const __half2*)&r1.y);
            a0 = fmaf(f00.x, c0, fmaf(f10.x, c1, a0));
            a1 = fmaf(f00.y, c0, fmaf(f10.y, c1, a1));
            a2 = fmaf(f01.x, c0, fmaf(f11.x, c1, a2));
            a3 = fmaf(f01.y, c0, fmaf(f11.y, c1, a3));
        }
        if (i < end) {
            int   s0 = g_srcx[i];
            float c0 = g_coef[i];
            uint2 r0 = *((const uint2*)(g_h1h + (size_t)s0 * FH) + lane);
            float2 f00 = __half22float2(*(const __half2*)&r0.x);
            float2 f01 = __half22float2(*(const __half2*)&r0.y);
            a0 = fmaf(f00.x, c0, a0);
            a1 = fmaf(f00.y, c0, a1);
            a2 = fmaf(f01.x, c0, a2);
            a3 = fmaf(f01.y, c0, a3);
        }
        *((float4*)(g_agg1 + (size_t)row * FH) + lane) = make_float4(a0, a1, a2, a3);
    }
}

// ---------------- BN1 statistics ----------------
#define BN1_NPB 128
__global__ void k_bn1_stats() {
    int j  = threadIdx.x;            // 0..127 feature
    int n0 = blockIdx.x * BN1_NPB;
    int n1 = n0 + BN1_NPB; if (n1 > NN) n1 = NN;
    float s = 0.f, q = 0.f;
    for (int n = n0; n < n1; n++) {
        float v = g_agg1[(size_t)n * FH + j];
        s += v;
        q = fmaf(v, v, q);
    }
    atomicAdd(&g_sum1[j], s);
    atomicAdd(&g_sq1[j], q);
}

__global__ void k_bn1_final(const float* __restrict__ gamma1, const float* __restrict__ beta1) {
    int j = threadIdx.x;
    float mean = g_sum1[j] * (1.f / NN);
    float var  = g_sq1[j] * (1.f / NN) - mean * mean;
    float sc   = gamma1[j] * rsqrtf(var + BN_EPS);
    g_scale1[j] = sc;
    g_shift1[j] = beta1[j] - mean * sc;
}

// ---------------- BN1 apply + ReLU + GEMM2 -> h2 ----------------
__global__ void k_layer2(const float* __restrict__ W2) {
    int gtid  = blockIdx.x * blockDim.x + threadIdx.x;
    int lane  = threadIdx.x & 31;
    int wid   = gtid >> 5;
    int nwarp = (gridDim.x * blockDim.x) >> 5;

    float4 sc = ((const float4*)g_scale1)[lane];
    float4 sh = ((const float4*)g_shift1)[lane];
    const float4* w4 = (const float4*)W2;
    float4 wA = w4[lane * 2];
    float4 wB = w4[lane * 2 + 1];

    for (int node = wid; node < NN; node += nwarp) {
        float4 x = *((const float4*)(g_agg1 + (size_t)node * FH) + lane);
        float y0 = fmaxf(fmaf(x.x, sc.x, sh.x), 0.f);
        float y1 = fmaxf(fmaf(x.y, sc.y, sh.y), 0.f);
        float y2 = fmaxf(fmaf(x.z, sc.z, sh.z), 0.f);
        float y3 = fmaxf(fmaf(x.w, sc.w, sh.w), 0.f);
        float p0 = y0 * wA.x + y1 * wA.z + y2 * wB.x + y3 * wB.z;
        float p1 = y0 * wA.y + y1 * wA.w + y2 * wB.y + y3 * wB.w;
#pragma unroll
        for (int o = 16; o; o >>= 1) {
            p0 += __shfl_xor_sync(0xffffffffu, p0, o);
            p1 += __shfl_xor_sync(0xffffffffu, p1, o);
        }
        if (lane == 0) {
            g_h2[(size_t)node * 2 + 0] = p0;
            g_h2[(size_t)node * 2 + 1] = p1;
        }
    }
}

// ---------------- layer-2 aggregation: CSR gather, thread per dst row ----------------
__global__ void k_agg2() {
    int stride = gridDim.x * blockDim.x;
    for (int row = blockIdx.x * blockDim.x + threadIdx.x; row < NN; row += stride) {
        int start = g_rowptr[row];
        int end   = g_rowptr[row + 1];
        float di  = g_dinv[row];
        float dd  = di * di;
        float2 h  = *(const float2*)(g_h2 + (size_t)row * 2);
        float a0 = h.x * dd, a1 = h.y * dd;
        for (int i = start; i < end; i++) {
            int   s = g_srcx[i];
            float c = g_coef[i];
            float2 hs = *(const float2*)(g_h2 + (size_t)s * 2);
            a0 = fmaf(hs.x, c, a0);
            a1 = fmaf(hs.y, c, a1);
        }
        g_agg2[(size_t)row * 2 + 0] = a0;
        g_agg2[(size_t)row * 2 + 1] = a1;
    }
}

// ---------------- BN2 statistics ----------------
__global__ void k_bn2_stats() {
    int gtid   = blockIdx.x * blockDim.x + threadIdx.x;
    int lane   = threadIdx.x & 31;
    int stride = gridDim.x * blockDim.x;
    float s0 = 0.f, q0 = 0.f, s1 = 0.f, q1 = 0.f;
    for (int n = gtid; n < NN; n += stride) {
        float2 a = *(const float2*)(g_agg2 + (size_t)n * 2);
        s0 += a.x; q0 = fmaf(a.x, a.x, q0);
        s1 += a.y; q1 = fmaf(a.y, a.y, q1);
    }
#pragma unroll
    for (int o = 16; o; o >>= 1) {
        s0 += __shfl_xor_sync(0xffffffffu, s0, o);
        q0 += __shfl_xor_sync(0xffffffffu, q0, o);
        s1 += __shfl_xor_sync(0xffffffffu, s1, o);
        q1 += __shfl_xor_sync(0xffffffffu, q1, o);
    }
    if (lane == 0) {
        atomicAdd(&g_sum2[0], s0); atomicAdd(&g_sq2[0], q0);
        atomicAdd(&g_sum2[1], s1); atomicAdd(&g_sq2[1], q1);
    }
}

// ---------------- BN2 + softmax ----------------
__global__ void k_out(const float* __restrict__ gamma2, const float* __restrict__ beta2,
                      float* __restrict__ out) {
    int i = blockIdx.x * blockDim.x + threadIdx.x;
    if (i >= NN) return;
    float m0 = g_sum2[0] * (1.f / NN);
    float v0 = g_sq2[0] * (1.f / NN) - m0 * m0;
    float m1 = g_sum2[1] * (1.f / NN);
    float v1 = g_sq2[1] * (1.f / NN) - m1 * m1;
    float sc0 = gamma2[0] * rsqrtf(v0 + BN_EPS);
    float sc1 = gamma2[1] * rsqrtf(v1 + BN_EPS);
    float sh0 = beta2[0] - m0 * sc0;
    float sh1 = beta2[1] - m1 * sc1;

    float2 a = *(const float2*)(g_agg2 + (size_t)i * 2);
    float y0 = fmaf(a.x, sc0, sh0);
    float y1 = fmaf(a.y, sc1, sh1);
    float mm = fmaxf(y0, y1);
    float e0 = expf(y0 - mm);
    float e1 = expf(y1 - mm);
    float inv = 1.f / (e0 + e1);
    ((float2*)out)[i] = make_float2(e0 * inv, e1 * inv);
}

// ---------------- launch ----------------
extern "C" void kernel_launch(void* const* d_in, const int* in_sizes, int n_in,
                              void* d_out, int out_size) {
    const int*   ew     = (const int*)  d_in[0];   // edge_index (int32 or int64, detected)
    const float* X      = (const float*)d_in[1];
    const float* uY     = (const float*)d_in[2];
    const float* W1     = (const float*)d_in[3];
    // d_in[4] = b1 (cancels under BatchNorm)
    const float* W2     = (const float*)d_in[5];
    // d_in[6] = b2 (cancels under BatchNorm)
    const float* gamma1 = (const float*)d_in[7];
    const float* beta1  = (const float*)d_in[8];
    const float* gamma2 = (const float*)d_in[9];
    const float* beta2  = (const float*)d_in[10];
    float* out = (float*)d_out;

    const int nscan = (NN + 1023) / 1024;   // 98

    k_init    <<<(NN + 255) / 256, 256>>>(ew);
    k_degree  <<<1024, 256>>>(ew);
    k_scan1   <<<nscan, 1024>>>();
    k_scan2   <<<1, 128>>>(nscan);
    k_scan3   <<<(NN + 255) / 256, 256>>>();
    k_scatter <<<1024, 256>>>(ew);
    k_gemm1   <<<(NN + 127) / 128, 256>>>(X, uY, W1);
    k_agg1    <<<2048, 256>>>();
    k_bn1_stats <<<(NN + BN1_NPB - 1) / BN1_NPB, 128>>>();
    k_bn1_final <<<1, 128>>>(gamma1, beta1);
    k_layer2  <<<2048, 256>>>(W2);
    k_agg2    <<<512, 256>>>();
    k_bn2_stats <<<256, 256>>>();
    k_out     <<<(NN + 255) / 256, 256>>>(gamma2, beta2, out);
}